// round 8
// baseline (speedup 1.0000x reference)
#include <cuda_runtime.h>
#include <cstdint>

#define NSEQ 2048
#define DD 512
#define VV 512
#define CL 16

// ---------------- device scratch ----------------
static __device__ float g_X [NSEQ * DD];
static __device__ float g_XW[NSEQ * DD];
static __device__ float g_G [NSEQ * DD];
static __device__ float g_H [NSEQ * DD];
static __device__ float g_O [NSEQ * VV];
static __device__ float g_E [VV * VV];
static __device__ int   g_cnt[NSEQ];
static __device__ int   g_is64;

// ---------------- helpers ----------------
__device__ __forceinline__ uint32_t ctarank() {
    uint32_t r; asm("mov.u32 %0, %%cluster_ctarank;" : "=r"(r)); return r;
}
__device__ __forceinline__ uint32_t s2u(const void* p) {
    uint32_t a;
    asm("{ .reg .u64 t; cvta.to.shared.u64 t, %1; cvt.u32.u64 %0, t; }" : "=r"(a) : "l"(p));
    return a;
}
__device__ __forceinline__ uint32_t mapa_(uint32_t laddr, uint32_t r) {
    uint32_t a; asm("mapa.shared::cluster.u32 %0, %1, %2;" : "=r"(a) : "r"(laddr), "r"(r));
    return a;
}
__device__ __forceinline__ void st_async64(uint32_t raddr, uint64_t v, uint32_t rmbar) {
    asm volatile("st.async.shared::cluster.mbarrier::complete_tx::bytes.b64 [%0], %1, [%2];"
                 :: "r"(raddr), "l"(v), "r"(rmbar) : "memory");
}
__device__ __forceinline__ void mbar_init(uint32_t mb, uint32_t cnt) {
    asm volatile("mbarrier.init.shared.b64 [%0], %1;" :: "r"(mb), "r"(cnt) : "memory");
}
__device__ __forceinline__ void mbar_expect(uint32_t mb, uint32_t bytes) {
    asm volatile("mbarrier.arrive.expect_tx.shared.b64 _, [%0], %1;" :: "r"(mb), "r"(bytes) : "memory");
}
__device__ __forceinline__ void mbar_wait(uint32_t mb, uint32_t parity) {
    asm volatile(
        "{\n\t.reg .pred P;\n"
        "W%=:\n\t"
        "mbarrier.try_wait.parity.acquire.cluster.shared::cta.b64 P, [%0], %1, 0x989680;\n\t"
        "@!P bra W%=;\n\t}"
        :: "r"(mb), "r"(parity) : "memory");
}
__device__ __forceinline__ void cl_sync() {
    asm volatile("barrier.cluster.arrive.aligned;" ::: "memory");
    asm volatile("barrier.cluster.wait.aligned;"   ::: "memory");
}
__device__ __forceinline__ int ld_acq(const int* p) {
    int v; asm volatile("ld.acquire.gpu.global.b32 %0, [%1];" : "=r"(v) : "l"(p) : "memory");
    return v;
}
__device__ __forceinline__ void red_rel(int* p) {
    asm volatile("red.release.gpu.global.add.u32 [%0], 1;" :: "l"(p) : "memory");
}
__device__ __forceinline__ float wsum(float x) {
#pragma unroll
    for (int o = 16; o; o >>= 1) x += __shfl_xor_sync(0xffffffffu, x, o);
    return x;
}
__device__ __forceinline__ float ex2f_(float x) {
    float y; asm("ex2.approx.f32 %0, %1;" : "=f"(y) : "f"(x)); return y;
}
__device__ __forceinline__ float lg2f_(float x) {
    float y; asm("lg2.approx.f32 %0, %1;" : "=f"(y) : "f"(x)); return y;
}
__device__ __forceinline__ float rcpf_(float x) {
    float y; asm("rcp.approx.f32 %0, %1;" : "=f"(y) : "f"(x)); return y;
}
__device__ __forceinline__ float tanh_ex2(float x) {     // 1 - 2/(e^2x+1)
    float t = ex2f_(2.8853900817779268f * x);
    float r = rcpf_(t + 1.0f);
    return fmaf(-2.0f, r, 1.0f);
}
__device__ __forceinline__ uint64_t pack2(float a, float b) {
    uint64_t d; asm("mov.b64 %0, {%1, %2};" : "=l"(d) : "f"(a), "f"(b)); return d;
}
__device__ __forceinline__ uint64_t fma2(uint64_t a, uint64_t b, uint64_t c) {
    uint64_t d; asm("fma.rn.f32x2 %0, %1, %2, %3;" : "=l"(d) : "l"(a), "l"(b), "l"(c));
    return d;
}
__device__ __forceinline__ float sum2(uint64_t v) {
    float lo, hi; asm("mov.b64 {%0, %1}, %2;" : "=f"(lo), "=f"(hi) : "l"(v));
    return lo + hi;
}

// ---------------- misc prep kernels ----------------
__global__ void detect_kernel(const int* __restrict__ w) {
    __shared__ int any;
    if (threadIdx.x == 0) any = 0;
    __syncthreads();
    int acc = 0;
    for (int i = threadIdx.x; i < NSEQ / 2; i += blockDim.x) acc |= w[2 * i + 1];
    if (acc) atomicOr(&any, 1);
    __syncthreads();
    if (threadIdx.x == 0) g_is64 = (any == 0) ? 1 : 0;
}

__global__ void gather_kernel(const void* __restrict__ nums, const float* __restrict__ emb) {
    int t = blockIdx.x;
    long long idx = g_is64 ? ((const long long*)nums)[t]
                           : (long long)((const int*)nums)[t];
    const float4* src = (const float4*)(emb + (size_t)idx * DD);
    float4* dst = (float4*)(&g_X[(size_t)t * DD]);
    dst[threadIdx.x] = src[threadIdx.x];      // blockDim = 128
}

__global__ void expT_kernel(const float* __restrict__ T) {
    int i = blockIdx.x * 256 + threadIdx.x;
    g_E[i] = ex2f_(T[i] * 1.4426950408889634f);
}

__global__ void zero_cnt_kernel() {
    g_cnt[blockIdx.x * 256 + threadIdx.x] = 0;
}

// ---------------- SIMT tiled SGEMM: C[2048,512] = A@B + bias ----------------
__global__ __launch_bounds__(256)
void gemm_bias(const float* __restrict__ A, const float* __restrict__ B,
               const float* __restrict__ bias, float* __restrict__ C)
{
    __shared__ __align__(16) float As[16][68];
    __shared__ __align__(16) float Bs[16][68];
    const int tid = threadIdx.x;
    const int bm = blockIdx.y * 64;
    const int bn = blockIdx.x * 64;
    const int tm = tid >> 4, tn = tid & 15;
    float acc[4][4] = {};
    for (int k0 = 0; k0 < 512; k0 += 16) {
        {
            int row = tid >> 2, cg = (tid & 3) * 4;
            float4 v = *(const float4*)(A + (size_t)(bm + row) * 512 + k0 + cg);
            As[cg + 0][row] = v.x; As[cg + 1][row] = v.y;
            As[cg + 2][row] = v.z; As[cg + 3][row] = v.w;
        }
        {
            int row = tid >> 4, col = (tid & 15) * 4;
            *(float4*)&Bs[row][col] = *(const float4*)(B + (size_t)(k0 + row) * 512 + bn + col);
        }
        __syncthreads();
#pragma unroll
        for (int k = 0; k < 16; k++) {
            float4 a = *(const float4*)&As[k][tm * 4];
            float4 b = *(const float4*)&Bs[k][tn * 4];
            float av[4] = {a.x, a.y, a.z, a.w};
            float bv[4] = {b.x, b.y, b.z, b.w};
#pragma unroll
            for (int i = 0; i < 4; i++)
#pragma unroll
                for (int jj = 0; jj < 4; jj++)
                    acc[i][jj] = fmaf(av[i], bv[jj], acc[i][jj]);
        }
        __syncthreads();
    }
    float4 bb = *(const float4*)(bias + bn + tn * 4);
#pragma unroll
    for (int i = 0; i < 4; i++) {
        float4 o;
        o.x = acc[i][0] + bb.x; o.y = acc[i][1] + bb.y;
        o.z = acc[i][2] + bb.z; o.w = acc[i][3] + bb.w;
        *(float4*)(C + (size_t)(bm + tm * 4 + i) * 512 + bn + tn * 4) = o;
    }
}

// State: plain [512], double-buffered. Warp w of CTA rank owns j0 = rank*32+2w,
// j1 = j0+1 (8B-aligned pair, one st.async.b64 per peer, sent by lanes 0..15
// of the warp itself — R3's proven parallel-issue pattern).
// Conflict-free read: ulonglong2 at [lane + 32*i]; k of pair = 128*i + 4*lane + 2*j.

// ---------------- fused 2-layer RNN: 2 clusters of 16 CTAs ----------------
// role 0 (blocks 0..15): layer 1. h-recurrence from XW1; writes G rows to
//   global + per-row release counter.
// role 1 (blocks 16..31): layer 2. Computes Wxh2^T g_t + b2 itself (polls the
//   counter; g prefetched one round ahead, off the critical path).
__global__ void __launch_bounds__(512, 1)
rnn_fused(const float* __restrict__ Whh1, const float* __restrict__ XW1,
          const float* __restrict__ Whh2, const float* __restrict__ Wxh2,
          const float* __restrict__ b2)
{
    __shared__ __align__(16) float sh[2 * 512];
    __shared__ __align__(8) long long mbar[2];
    const int tid  = threadIdx.x;
    const int lane = tid & 31;
    const int w    = tid >> 5;
    const uint32_t rank = ctarank();
    const int role = blockIdx.x >> 4;
    const int j0 = (int)rank * 32 + 2 * w;

    for (int i = tid; i < 2 * 512; i += 512) sh[i] = 0.0f;   // h0 = 0
    const uint32_t base = s2u(sh);
    const uint32_t mb0  = s2u(&mbar[0]);
    if (tid == 0) {
        mbar_init(mb0, 1);      mbar_init(mb0 + 8, 1);
        mbar_expect(mb0, 2048); mbar_expect(mb0 + 8, 2048);
    }
    __syncthreads();
    cl_sync();

    uint32_t rA = 0, rM = 0;
    if (lane < CL) {
        rA = mapa_(base + (uint32_t)(rank * 128u + 8u * w), (uint32_t)lane);
        rM = mapa_(mb0, (uint32_t)lane);
    }

    if (role == 0) {
        // ---- layer 1 ----
        const float* Whh = Whh1;
        uint64_t w0p[8], w1p[8];
#pragma unroll
        for (int i = 0; i < 4; i++)
#pragma unroll
            for (int j = 0; j < 2; j++) {
                int k = 128 * i + 4 * lane + 2 * j;
                w0p[2 * i + j] = pack2(Whh[(size_t)k * DD + j0],
                                       Whh[(size_t)(k + 1) * DD + j0]);
                w1p[2 * i + j] = pack2(Whh[(size_t)k * DD + j0 + 1],
                                       Whh[(size_t)(k + 1) * DD + j0 + 1]);
            }
        float2 xw = *(const float2*)&XW1[j0];

#pragma unroll 1
        for (int t = 0; t < NSEQ; t++) {
            const uint32_t p = (uint32_t)(t & 1);
            if (t) {
                mbar_wait(mb0 + 8 * p, (uint32_t)(((t - 1) >> 1) & 1));
                if (tid == 0) mbar_expect(mb0 + 8 * p, 2048);
            }
            const ulonglong2* cb = (const ulonglong2*)(sh + p * 512);
            ulonglong2 A = cb[lane], B = cb[lane + 32], C = cb[lane + 64], D = cb[lane + 96];
            uint64_t p0 = 0, p1 = 0, q0 = 0, q1 = 0;
            p0 = fma2(A.x, w0p[0], p0);  p1 = fma2(A.y, w0p[1], p1);
            q0 = fma2(A.x, w1p[0], q0);  q1 = fma2(A.y, w1p[1], q1);
            p0 = fma2(B.x, w0p[2], p0);  p1 = fma2(B.y, w0p[3], p1);
            q0 = fma2(B.x, w1p[2], q0);  q1 = fma2(B.y, w1p[3], q1);
            p0 = fma2(C.x, w0p[4], p0);  p1 = fma2(C.y, w0p[5], p1);
            q0 = fma2(C.x, w1p[4], q0);  q1 = fma2(C.y, w1p[5], q1);
            p0 = fma2(D.x, w0p[6], p0);  p1 = fma2(D.y, w0p[7], p1);
            q0 = fma2(D.x, w1p[6], q0);  q1 = fma2(D.y, w1p[7], q1);
            float ps = wsum(sum2(p0) + sum2(p1));
            float qs = wsum(sum2(q0) + sum2(q1));
            float h0 = tanh_ex2(xw.x + ps);
            float h1 = tanh_ex2(xw.y + qs);

            if (lane == 0) {          // hand G row piece to layer 2 ASAP
                *(float2*)&g_G[(size_t)t * DD + j0] = make_float2(h0, h1);
                red_rel(&g_cnt[t]);   // release-counted (256 warps per row)
            }
            if (t + 1 < NSEQ) {
                const uint32_t np = (uint32_t)((t + 1) & 1);
                if (lane < CL) st_async64(rA + np * 2048u, pack2(h0, h1), rM + 8u * np);
                xw = *(const float2*)&XW1[(size_t)(t + 1) * DD + j0];
            }
        }
    } else {
        // ---- layer 2 ----
        uint64_t w0p[8], w1p[8], x0p[8], x1p[8];
#pragma unroll
        for (int i = 0; i < 4; i++)
#pragma unroll
            for (int j = 0; j < 2; j++) {
                int k = 128 * i + 4 * lane + 2 * j;
                w0p[2 * i + j] = pack2(Whh2[(size_t)k * DD + j0],
                                       Whh2[(size_t)(k + 1) * DD + j0]);
                w1p[2 * i + j] = pack2(Whh2[(size_t)k * DD + j0 + 1],
                                       Whh2[(size_t)(k + 1) * DD + j0 + 1]);
                x0p[2 * i + j] = pack2(Wxh2[(size_t)k * DD + j0],
                                       Wxh2[(size_t)(k + 1) * DD + j0]);
                x1p[2 * i + j] = pack2(Wxh2[(size_t)k * DD + j0 + 1],
                                       Wxh2[(size_t)(k + 1) * DD + j0 + 1]);
            }
        const float bj0 = b2[j0], bj1 = b2[j0 + 1];

        // prefetch input partials for t = 0
        uint64_t ip0, ip1, iq0, iq1;
        {
            while (ld_acq(&g_cnt[0]) < 256) {}
            const ulonglong2* gg = (const ulonglong2*)&g_G[0];
            ulonglong2 A = gg[lane], B = gg[lane + 32], C = gg[lane + 64], D = gg[lane + 96];
            ip0 = ip1 = iq0 = iq1 = 0;
            ip0 = fma2(A.x, x0p[0], ip0);  ip1 = fma2(A.y, x0p[1], ip1);
            iq0 = fma2(A.x, x1p[0], iq0);  iq1 = fma2(A.y, x1p[1], iq1);
            ip0 = fma2(B.x, x0p[2], ip0);  ip1 = fma2(B.y, x0p[3], ip1);
            iq0 = fma2(B.x, x1p[2], iq0);  iq1 = fma2(B.y, x1p[3], iq1);
            ip0 = fma2(C.x, x0p[4], ip0);  ip1 = fma2(C.y, x0p[5], ip1);
            iq0 = fma2(C.x, x1p[4], iq0);  iq1 = fma2(C.y, x1p[5], iq1);
            ip0 = fma2(D.x, x0p[6], ip0);  ip1 = fma2(D.y, x0p[7], ip1);
            iq0 = fma2(D.x, x1p[6], iq0);  iq1 = fma2(D.y, x1p[7], iq1);
        }

#pragma unroll 1
        for (int t = 0; t < NSEQ; t++) {
            const uint32_t p = (uint32_t)(t & 1);
            if (t) {
                mbar_wait(mb0 + 8 * p, (uint32_t)(((t - 1) >> 1) & 1));
                if (tid == 0) mbar_expect(mb0 + 8 * p, 2048);
            }
            const ulonglong2* cb = (const ulonglong2*)(sh + p * 512);
            ulonglong2 A = cb[lane], B = cb[lane + 32], C = cb[lane + 64], D = cb[lane + 96];
            uint64_t p0 = ip0, p1 = ip1, q0 = iq0, q1 = iq1;
            p0 = fma2(A.x, w0p[0], p0);  p1 = fma2(A.y, w0p[1], p1);
            q0 = fma2(A.x, w1p[0], q0);  q1 = fma2(A.y, w1p[1], q1);
            p0 = fma2(B.x, w0p[2], p0);  p1 = fma2(B.y, w0p[3], p1);
            q0 = fma2(B.x, w1p[2], q0);  q1 = fma2(B.y, w1p[3], q1);
            p0 = fma2(C.x, w0p[4], p0);  p1 = fma2(C.y, w0p[5], p1);
            q0 = fma2(C.x, w1p[4], q0);  q1 = fma2(C.y, w1p[5], q1);
            p0 = fma2(D.x, w0p[6], p0);  p1 = fma2(D.y, w0p[7], p1);
            q0 = fma2(D.x, w1p[6], q0);  q1 = fma2(D.y, w1p[7], q1);
            float ps = wsum(sum2(p0) + sum2(p1));
            float qs = wsum(sum2(q0) + sum2(q1));
            float h0 = tanh_ex2(ps + bj0);
            float h1 = tanh_ex2(qs + bj1);

            if (lane == 0) *(float2*)&g_H[(size_t)t * DD + j0] = make_float2(h0, h1);
            if (t + 1 < NSEQ) {
                const uint32_t np = (uint32_t)((t + 1) & 1);
                if (lane < CL) st_async64(rA + np * 2048u, pack2(h0, h1), rM + 8u * np);
                // prefetch g_{t+1} input partials (off critical path)
                while (ld_acq(&g_cnt[t + 1]) < 256) {}
                const ulonglong2* gg = (const ulonglong2*)&g_G[(size_t)(t + 1) * DD];
                ulonglong2 GA = gg[lane], GB = gg[lane + 32], GC = gg[lane + 64], GD = gg[lane + 96];
                ip0 = ip1 = iq0 = iq1 = 0;
                ip0 = fma2(GA.x, x0p[0], ip0);  ip1 = fma2(GA.y, x0p[1], ip1);
                iq0 = fma2(GA.x, x1p[0], iq0);  iq1 = fma2(GA.y, x1p[1], iq1);
                ip0 = fma2(GB.x, x0p[2], ip0);  ip1 = fma2(GB.y, x0p[3], ip1);
                iq0 = fma2(GB.x, x1p[2], iq0);  iq1 = fma2(GB.y, x1p[3], iq1);
                ip0 = fma2(GC.x, x0p[4], ip0);  ip1 = fma2(GC.y, x0p[5], ip1);
                iq0 = fma2(GC.x, x1p[4], iq0);  iq1 = fma2(GC.y, x1p[5], iq1);
                ip0 = fma2(GD.x, x0p[6], ip0);  ip1 = fma2(GD.y, x0p[7], ip1);
                iq0 = fma2(GD.x, x1p[6], iq0);  iq1 = fma2(GD.y, x1p[7], iq1);
            }
        }
    }
    cl_sync();
}

// ---------------- CRF backward: R3 comm + f32x2, exp(T)-factored ----------------
__global__ void __launch_bounds__(512, 1)
crf16(float* __restrict__ out)
{
    __shared__ __align__(16) float sh[2 * 512];
    __shared__ __align__(16) float eb[2 * 512];
    __shared__ __align__(8) long long mbar[2];
    const int tid  = threadIdx.x;
    const int lane = tid & 31;
    const int w    = tid >> 5;
    const uint32_t rank = ctarank();
    const int u0 = (int)rank * 32 + 2 * w;
    const float L2E = 1.4426950408889634f;
    const float LN2 = 0.6931471805599453f;
    const float* O = g_O;

    uint64_t e0p[8], e1p[8];
#pragma unroll
    for (int i = 0; i < 4; i++)
#pragma unroll
        for (int j = 0; j < 2; j++) {
            int k = 128 * i + 4 * lane + 2 * j;
            e0p[2 * i + j] = pack2(g_E[(size_t)u0 * VV + k],
                                   g_E[(size_t)u0 * VV + k + 1]);
            e1p[2 * i + j] = pack2(g_E[(size_t)(u0 + 1) * VV + k],
                                   g_E[(size_t)(u0 + 1) * VV + k + 1]);
        }
    for (int i = tid; i < 2 * 512; i += 512) sh[i] = -1.0e30f;

    const uint32_t base = s2u(sh);
    const uint32_t mb0  = s2u(&mbar[0]);
    if (tid == 0) {
        sh[1] = O[(size_t)(NSEQ - 1) * VV + 1] * L2E;   // c_init[EOS] (log2 units)
        mbar_init(mb0, 1);      mbar_init(mb0 + 8, 1);
        mbar_expect(mb0, 2048); mbar_expect(mb0 + 8, 2048);
    }
    __syncthreads();
    cl_sync();

    uint32_t rA = 0, rM = 0;
    if (lane < CL) {
        rA = mapa_(base + (uint32_t)(rank * 128u + 8u * w), (uint32_t)lane);
        rM = mapa_(mb0, (uint32_t)lane);
    }

    float2 ov = *(const float2*)&O[(size_t)(NSEQ - 2) * VV + u0];
    float o0 = ov.x * L2E, o1 = ov.y * L2E;

#pragma unroll 1
    for (int si = 0; si < NSEQ - 1; si++) {
        const uint32_t p = (uint32_t)(si & 1);
        if (si) {
            mbar_wait(mb0 + 8 * p, (uint32_t)(((si - 1) >> 1) & 1));
            if (tid == 0) mbar_expect(mb0 + 8 * p, 2048);
        }
        const float* cbuf = sh + p * 512;
        float* ebuf = eb + p * 512;
        const float offc = cbuf[1];                    // c[EOS] (log2 units)
        ebuf[tid] = ex2f_(cbuf[tid] - offc);
        __syncthreads();

        const ulonglong2* ep = (const ulonglong2*)ebuf;
        ulonglong2 A = ep[lane], B = ep[lane + 32], C = ep[lane + 64], D = ep[lane + 96];
        uint64_t p0 = 0, p1 = 0, q0 = 0, q1 = 0;
        p0 = fma2(A.x, e0p[0], p0);  p1 = fma2(A.y, e0p[1], p1);
        q0 = fma2(A.x, e1p[0], q0);  q1 = fma2(A.y, e1p[1], q1);
        p0 = fma2(B.x, e0p[2], p0);  p1 = fma2(B.y, e0p[3], p1);
        q0 = fma2(B.x, e1p[2], q0);  q1 = fma2(B.y, e1p[3], q1);
        p0 = fma2(C.x, e0p[4], p0);  p1 = fma2(C.y, e0p[5], p1);
        q0 = fma2(C.x, e1p[4], q0);  q1 = fma2(C.y, e1p[5], q1);
        p0 = fma2(D.x, e0p[6], p0);  p1 = fma2(D.y, e0p[7], p1);
        q0 = fma2(D.x, e1p[6], q0);  q1 = fma2(D.y, e1p[7], q1);
        float s0 = wsum(sum2(p0) + sum2(p1));
        float s1 = wsum(sum2(q0) + sum2(q1));
        float cl0 = o0 + offc + lg2f_(s0);
        float cl1 = o1 + offc + lg2f_(s1);

        if (si == NSEQ - 2) {
            if (rank == 0 && tid == 0) out[0] = cl0 * LN2;   // c0[BOS]
        } else {
            const uint32_t np = (uint32_t)((si + 1) & 1);
            if (lane < CL) st_async64(rA + np * 2048u, pack2(cl0 * 1.0f, cl1) , rM + 8u * np);
            int row = NSEQ - 3 - si;
            float2 onx = *(const float2*)&O[(size_t)row * VV + u0];
            o0 = onx.x * L2E; o1 = onx.y * L2E;
        }
    }
    cl_sync();
}

// ---------------- launch ----------------
extern "C" void kernel_launch(void* const* d_in, const int* in_sizes, int n_in,
                              void* d_out, int out_size)
{
    const void*  nums = d_in[0];
    const float* emb  = (const float*)d_in[1];
    const float* Wxh1 = (const float*)d_in[2];
    const float* Whh1 = (const float*)d_in[3];
    const float* b1   = (const float*)d_in[4];
    const float* Wxh2 = (const float*)d_in[5];
    const float* Whh2 = (const float*)d_in[6];
    const float* b2   = (const float*)d_in[7];
    const float* Wl   = (const float*)d_in[8];
    const float* bl   = (const float*)d_in[9];
    const float* Tm   = (const float*)d_in[10];
    float* out = (float*)d_out;

    float *X, *XW, *G, *H, *O;
    cudaGetSymbolAddress((void**)&X,  g_X);
    cudaGetSymbolAddress((void**)&XW, g_XW);
    cudaGetSymbolAddress((void**)&G,  g_G);
    cudaGetSymbolAddress((void**)&H,  g_H);
    cudaGetSymbolAddress((void**)&O,  g_O);

    cudaFuncSetAttribute((const void*)rnn_fused, cudaFuncAttributeNonPortableClusterSizeAllowed, 1);
    cudaFuncSetAttribute((const void*)crf16,     cudaFuncAttributeNonPortableClusterSizeAllowed, 1);

    detect_kernel<<<1, 256>>>((const int*)nums);
    gather_kernel<<<NSEQ, 128>>>(nums, emb);
    expT_kernel<<<VV * VV / 256, 256>>>(Tm);
    zero_cnt_kernel<<<NSEQ / 256, 256>>>();

    dim3 gg(512 / 64, NSEQ / 64);
    gemm_bias<<<gg, 256>>>(X, Wxh1, b1, XW);      // XW1 = X@Wxh1 + b1

    cudaLaunchConfig_t cfg = {};
    cfg.blockDim = dim3(512, 1, 1);
    cfg.dynamicSmemBytes = 0;
    cfg.stream = 0;
    cudaLaunchAttribute at[1];
    at[0].id = cudaLaunchAttributeClusterDimension;
    at[0].val.clusterDim.x = CL;
    at[0].val.clusterDim.y = 1;
    at[0].val.clusterDim.z = 1;
    cfg.attrs = at;
    cfg.numAttrs = 1;

    // fused two-layer RNN: 2 clusters of 16
    cfg.gridDim = dim3(2 * CL, 1, 1);
    cudaLaunchKernelEx(&cfg, rnn_fused, Whh1, (const float*)XW, Whh2, Wxh2, b2);

    gemm_bias<<<gg, 256>>>(H, Wl, bl, O);         // O = H@Wl + bl

    cfg.gridDim = dim3(CL, 1, 1);
    cudaLaunchKernelEx(&cfg, crf16, out);         // c0[BOS]
}

// round 9
// speedup vs baseline: 1.1320x; 1.1320x over previous
#include <cuda_runtime.h>
#include <cstdint>

#define NSEQ 2048
#define DD 512
#define VV 512
#define CL 16

static __device__ float g_X [NSEQ * DD];
static __device__ float g_XW[NSEQ * DD];
static __device__ float g_H [NSEQ * DD];
static __device__ float g_O [NSEQ * VV];
static __device__ float g_E [VV * VV];
static __device__ int   g_is64;

__device__ __forceinline__ uint32_t ctarank() {
    uint32_t r; asm("mov.u32 %0, %%cluster_ctarank;" : "=r"(r)); return r;
}
__device__ __forceinline__ uint32_t s2u(const void* p) {
    uint32_t a;
    asm("{ .reg .u64 t; cvta.to.shared.u64 t, %1; cvt.u32.u64 %0, t; }" : "=r"(a) : "l"(p));
    return a;
}
__device__ __forceinline__ uint32_t mapa_(uint32_t laddr, uint32_t r) {
    uint32_t a; asm("mapa.shared::cluster.u32 %0, %1, %2;" : "=r"(a) : "r"(laddr), "r"(r));
    return a;
}
__device__ __forceinline__ void st_async64(uint32_t raddr, uint64_t v, uint32_t rmbar) {
    asm volatile("st.async.shared::cluster.mbarrier::complete_tx::bytes.b64 [%0], %1, [%2];"
                 :: "r"(raddr), "l"(v), "r"(rmbar) : "memory");
}
__device__ __forceinline__ void mbar_init(uint32_t mb, uint32_t cnt) {
    asm volatile("mbarrier.init.shared.b64 [%0], %1;" :: "r"(mb), "r"(cnt) : "memory");
}
__device__ __forceinline__ void mbar_expect(uint32_t mb, uint32_t bytes) {
    asm volatile("mbarrier.arrive.expect_tx.shared.b64 _, [%0], %1;" :: "r"(mb), "r"(bytes) : "memory");
}
__device__ __forceinline__ void mbar_wait(uint32_t mb, uint32_t parity) {
    asm volatile(
        "{\n\t.reg .pred P;\n"
        "W%=:\n\t"
        "mbarrier.try_wait.parity.acquire.cluster.shared::cta.b64 P, [%0], %1, 0x989680;\n\t"
        "@!P bra W%=;\n\t}"
        :: "r"(mb), "r"(parity) : "memory");
}
__device__ __forceinline__ void cl_sync() {
    asm volatile("barrier.cluster.arrive.aligned;" ::: "memory");
    asm volatile("barrier.cluster.wait.aligned;"   ::: "memory");
}
__device__ __forceinline__ float wsum(float x) {
#pragma unroll
    for (int o = 16; o; o >>= 1) x += __shfl_xor_sync(0xffffffffu, x, o);
    return x;
}
__device__ __forceinline__ float ex2f_(float x) {
    float y; asm("ex2.approx.f32 %0, %1;" : "=f"(y) : "f"(x)); return y;
}
__device__ __forceinline__ float lg2f_(float x) {
    float y; asm("lg2.approx.f32 %0, %1;" : "=f"(y) : "f"(x)); return y;
}
__device__ __forceinline__ float rcpf_(float x) {
    float y; asm("rcp.approx.f32 %0, %1;" : "=f"(y) : "f"(x)); return y;
}
__device__ __forceinline__ float tanh_ex2(float x) {
    float t = ex2f_(2.8853900817779268f * x);
    float r = rcpf_(t + 1.0f);
    return fmaf(-2.0f, r, 1.0f);
}
__device__ __forceinline__ uint64_t pack2(float a, float b) {
    uint64_t d; asm("mov.b64 %0, {%1, %2};" : "=l"(d) : "f"(a), "f"(b)); return d;
}
__device__ __forceinline__ uint64_t fma2(uint64_t a, uint64_t b, uint64_t c) {
    uint64_t d; asm("fma.rn.f32x2 %0, %1, %2, %3;" : "=l"(d) : "l"(a), "l"(b), "l"(c));
    return d;
}
__device__ __forceinline__ float sum2(uint64_t v) {
    float lo, hi; asm("mov.b64 {%0, %1}, %2;" : "=f"(lo), "=f"(hi) : "l"(v));
    return lo + hi;
}

__global__ void detect_kernel(const int* __restrict__ w) {
    __shared__ int any;
    if (threadIdx.x == 0) any = 0;
    __syncthreads();
    int acc = 0;
    for (int i = threadIdx.x; i < NSEQ / 2; i += blockDim.x) acc |= w[2 * i + 1];
    if (acc) atomicOr(&any, 1);
    __syncthreads();
    if (threadIdx.x == 0) g_is64 = (any == 0) ? 1 : 0;
}

__global__ void gather_kernel(const void* __restrict__ nums, const float* __restrict__ emb) {
    int t = blockIdx.x;
    long long idx = g_is64 ? ((const long long*)nums)[t]
                           : (long long)((const int*)nums)[t];
    const float4* src = (const float4*)(emb + (size_t)idx * DD);
    float4* dst = (float4*)(&g_X[(size_t)t * DD]);
    dst[threadIdx.x] = src[threadIdx.x];
}

__global__ void expT_kernel(const float* __restrict__ T) {
    int i = blockIdx.x * 256 + threadIdx.x;
    g_E[i] = ex2f_(T[i] * 1.4426950408889634f);
}

__global__ __launch_bounds__(256)
void gemm_bias(const float* __restrict__ A, const float* __restrict__ B,
               const float* __restrict__ bias, float* __restrict__ C)
{
    __shared__ __align__(16) float As[16][68];
    __shared__ __align__(16) float Bs[16][68];
    const int tid = threadIdx.x;
    const int bm = blockIdx.y * 64, bn = blockIdx.x * 64;
    const int tm = tid >> 4, tn = tid & 15;
    float acc[4][4] = {};
    for (int k0 = 0; k0 < 512; k0 += 16) {
        {
            int row = tid >> 2, cg = (tid & 3) * 4;
            float4 v = *(const float4*)(A + (size_t)(bm + row) * 512 + k0 + cg);
            As[cg + 0][row] = v.x; As[cg + 1][row] = v.y;
            As[cg + 2][row] = v.z; As[cg + 3][row] = v.w;
        }
        {
            int row = tid >> 4, col = (tid & 15) * 4;
            *(float4*)&Bs[row][col] = *(const float4*)(B + (size_t)(k0 + row) * 512 + bn + col);
        }
        __syncthreads();
#pragma unroll
        for (int k = 0; k < 16; k++) {
            float4 a = *(const float4*)&As[k][tm * 4];
            float4 b = *(const float4*)&Bs[k][tn * 4];
            float av[4] = {a.x, a.y, a.z, a.w};
            float bv[4] = {b.x, b.y, b.z, b.w};
#pragma unroll
            for (int i = 0; i < 4; i++)
#pragma unroll
                for (int jj = 0; jj < 4; jj++)
                    acc[i][jj] = fmaf(av[i], bv[jj], acc[i][jj]);
        }
        __syncthreads();
    }
    float4 bb = *(const float4*)(bias + bn + tn * 4);
#pragma unroll
    for (int i = 0; i < 4; i++) {
        float4 o;
        o.x = acc[i][0] + bb.x; o.y = acc[i][1] + bb.y;
        o.z = acc[i][2] + bb.z; o.w = acc[i][3] + bb.w;
        *(float4*)(C + (size_t)(bm + tm * 4 + i) * 512 + bn + tn * 4) = o;
    }
}

// ---- fused 2-layer RNN, one 16-CTA cluster ----
// sh1: h1 state (double-buffered), sh2: h2 state. Warp w owns pairs j0=rank*32+2w
// for BOTH layers. Round r: h1_r = tanh(XW1[r] + Whh1^T h1_{r-1}) [send first];
// h2_{r-1} = tanh(Wxh2^T h1_{r-1} + Whh2^T h2_{r-2} + b2). mbar[0..1]=h1 bufs,
// mbar[2..3]=h2 bufs, each expects 2048 B (256 pair-messages).
__global__ void __launch_bounds__(512, 1)
rnn_fused2(const float* __restrict__ Whh1, const float* __restrict__ XW1,
           const float* __restrict__ Whh2, const float* __restrict__ Wxh2,
           const float* __restrict__ b2, float* __restrict__ Hout)
{
    __shared__ __align__(16) float sh1[2 * 512];
    __shared__ __align__(16) float sh2[2 * 512];
    __shared__ __align__(8) long long mbar[4];
    const int tid  = threadIdx.x;
    const int lane = tid & 31;
    const int w    = tid >> 5;
    const uint32_t rank = ctarank();
    const int j0 = (int)rank * 32 + 2 * w;

    uint64_t w1a[8], w1b[8], xa[8], xb[8], ha[8], hb[8];
#pragma unroll
    for (int i = 0; i < 4; i++)
#pragma unroll
        for (int j = 0; j < 2; j++) {
            int k = 128 * i + 4 * lane + 2 * j;
            w1a[2*i+j] = pack2(Whh1[(size_t)k*DD + j0],   Whh1[(size_t)(k+1)*DD + j0]);
            w1b[2*i+j] = pack2(Whh1[(size_t)k*DD + j0+1], Whh1[(size_t)(k+1)*DD + j0+1]);
            xa [2*i+j] = pack2(Wxh2[(size_t)k*DD + j0],   Wxh2[(size_t)(k+1)*DD + j0]);
            xb [2*i+j] = pack2(Wxh2[(size_t)k*DD + j0+1], Wxh2[(size_t)(k+1)*DD + j0+1]);
            ha [2*i+j] = pack2(Whh2[(size_t)k*DD + j0],   Whh2[(size_t)(k+1)*DD + j0]);
            hb [2*i+j] = pack2(Whh2[(size_t)k*DD + j0+1], Whh2[(size_t)(k+1)*DD + j0+1]);
        }
    const float bj0 = b2[j0], bj1 = b2[j0 + 1];
    for (int i = tid; i < 2 * 512; i += 512) { sh1[i] = 0.0f; sh2[i] = 0.0f; }

    const uint32_t b1 = s2u(sh1);
    const uint32_t b2s = s2u(sh2);
    const uint32_t mb = s2u(mbar);
    if (tid == 0) {
#pragma unroll
        for (int q = 0; q < 4; q++) { mbar_init(mb + 8*q, 1); }
#pragma unroll
        for (int q = 0; q < 4; q++) { mbar_expect(mb + 8*q, 2048); }
    }
    __syncthreads();
    cl_sync();

    uint32_t rA1 = 0, rA2 = 0, rM = 0;
    if (lane < CL) {
        rA1 = mapa_(b1 + rank * 128u + 8u * (uint32_t)w, (uint32_t)lane);
        rA2 = mapa_(b2s + rank * 128u + 8u * (uint32_t)w, (uint32_t)lane);
        rM  = mapa_(mb, (uint32_t)lane);
    }
    float2 xw = *(const float2*)&XW1[j0];

#pragma unroll 1
    for (int r = 0; r <= NSEQ; r++) {
        const uint32_t p = (uint32_t)(r & 1), np = (uint32_t)((r + 1) & 1);
        const uint32_t ph = (uint32_t)(((r - 1) >> 1) & 1);
        if (r) {
            mbar_wait(mb + 8 * p, ph);
            if (tid == 0) mbar_expect(mb + 8 * p, 2048);
        }
        // load h1_{r-1}
        const ulonglong2* c1 = (const ulonglong2*)(sh1 + p * 512);
        ulonglong2 A = c1[lane], B = c1[lane + 32], C = c1[lane + 64], D = c1[lane + 96];

        // h1 chain first (critical): matvec + send
        if (r < NSEQ) {
            uint64_t p0=0,p1=0,q0=0,q1=0;
            p0=fma2(A.x,w1a[0],p0); p1=fma2(A.y,w1a[1],p1);
            q0=fma2(A.x,w1b[0],q0); q1=fma2(A.y,w1b[1],q1);
            p0=fma2(B.x,w1a[2],p0); p1=fma2(B.y,w1a[3],p1);
            q0=fma2(B.x,w1b[2],q0); q1=fma2(B.y,w1b[3],q1);
            p0=fma2(C.x,w1a[4],p0); p1=fma2(C.y,w1a[5],p1);
            q0=fma2(C.x,w1b[4],q0); q1=fma2(C.y,w1b[5],q1);
            p0=fma2(D.x,w1a[6],p0); p1=fma2(D.y,w1a[7],p1);
            q0=fma2(D.x,w1b[6],q0); q1=fma2(D.y,w1b[7],q1);
            float ps = wsum(sum2(p0) + sum2(p1));
            float qs = wsum(sum2(q0) + sum2(q1));
            float a0 = tanh_ex2(xw.x + ps);
            float a1 = tanh_ex2(xw.y + qs);
            if (lane < CL) st_async64(rA1 + np * 2048u, pack2(a0, a1), rM + 8u * np);
        }
        // h2 input matvec from same h1_{r-1} regs
        uint64_t u0=0,u1=0,v0=0,v1=0;
        u0=fma2(A.x,xa[0],u0); u1=fma2(A.y,xa[1],u1);
        v0=fma2(A.x,xb[0],v0); v1=fma2(A.y,xb[1],v1);
        u0=fma2(B.x,xa[2],u0); u1=fma2(B.y,xa[3],u1);
        v0=fma2(B.x,xb[2],v0); v1=fma2(B.y,xb[3],v1);
        u0=fma2(C.x,xa[4],u0); u1=fma2(C.y,xa[5],u1);
        v0=fma2(C.x,xb[4],v0); v1=fma2(C.y,xb[5],v1);
        u0=fma2(D.x,xa[6],u0); u1=fma2(D.y,xa[7],u1);
        v0=fma2(D.x,xb[6],v0); v1=fma2(D.y,xb[7],v1);

        if (r >= 1) {
            mbar_wait(mb + 16 + 8 * p, ph);
            if (tid == 0) mbar_expect(mb + 16 + 8 * p, 2048);
            const ulonglong2* c2 = (const ulonglong2*)(sh2 + p * 512);
            ulonglong2 E = c2[lane], F = c2[lane + 32], G = c2[lane + 64], H = c2[lane + 96];
            u0=fma2(E.x,ha[0],u0); u1=fma2(E.y,ha[1],u1);
            v0=fma2(E.x,hb[0],v0); v1=fma2(E.y,hb[1],v1);
            u0=fma2(F.x,ha[2],u0); u1=fma2(F.y,ha[3],u1);
            v0=fma2(F.x,hb[2],v0); v1=fma2(F.y,hb[3],v1);
            u0=fma2(G.x,ha[4],u0); u1=fma2(G.y,ha[5],u1);
            v0=fma2(G.x,hb[4],v0); v1=fma2(G.y,hb[5],v1);
            u0=fma2(H.x,ha[6],u0); u1=fma2(H.y,ha[7],u1);
            v0=fma2(H.x,hb[6],v0); v1=fma2(H.y,hb[7],v1);
            float us = wsum(sum2(u0) + sum2(u1));
            float vs = wsum(sum2(v0) + sum2(v1));
            float h0 = tanh_ex2(us + bj0);
            float h1 = tanh_ex2(vs + bj1);
            if (lane == 0) *(float2*)&Hout[(size_t)(r - 1) * DD + j0] = make_float2(h0, h1);
            if (r < NSEQ && lane < CL)
                st_async64(rA2 + np * 2048u, pack2(h0, h1), rM + 16u + 8u * np);
        } else {
            // h2_{-1} = 0
            if (lane < CL) st_async64(rA2 + np * 2048u, 0ull, rM + 16u + 8u * np);
        }
        if (r + 1 < NSEQ) xw = *(const float2*)&XW1[(size_t)(r + 1) * DD + j0];
    }
    cl_sync();
}

// ---- CRF backward (proven R3 comm + f32x2, exp(T)-factored) ----
__global__ void __launch_bounds__(512, 1)
crf16(float* __restrict__ out)
{
    __shared__ __align__(16) float sh[2 * 512];
    __shared__ __align__(16) float eb[2 * 512];
    __shared__ __align__(8) long long mbar[2];
    const int tid  = threadIdx.x;
    const int lane = tid & 31;
    const int w    = tid >> 5;
    const uint32_t rank = ctarank();
    const int u0 = (int)rank * 32 + 2 * w;
    const float L2E = 1.4426950408889634f;
    const float LN2 = 0.6931471805599453f;
    const float* O = g_O;

    uint64_t e0p[8], e1p[8];
#pragma unroll
    for (int i = 0; i < 4; i++)
#pragma unroll
        for (int j = 0; j < 2; j++) {
            int k = 128 * i + 4 * lane + 2 * j;
            e0p[2*i+j] = pack2(g_E[(size_t)u0*VV + k],     g_E[(size_t)u0*VV + k + 1]);
            e1p[2*i+j] = pack2(g_E[(size_t)(u0+1)*VV + k], g_E[(size_t)(u0+1)*VV + k + 1]);
        }
    for (int i = tid; i < 2 * 512; i += 512) sh[i] = -1.0e30f;

    const uint32_t base = s2u(sh);
    const uint32_t mb0  = s2u(&mbar[0]);
    if (tid == 0) {
        sh[1] = O[(size_t)(NSEQ - 1) * VV + 1] * L2E;
        mbar_init(mb0, 1);      mbar_init(mb0 + 8, 1);
        mbar_expect(mb0, 2048); mbar_expect(mb0 + 8, 2048);
    }
    __syncthreads();
    cl_sync();

    uint32_t rA = 0, rM = 0;
    if (lane < CL) {
        rA = mapa_(base + rank * 128u + 8u * (uint32_t)w, (uint32_t)lane);
        rM = mapa_(mb0, (uint32_t)lane);
    }
    float2 ov = *(const float2*)&O[(size_t)(NSEQ - 2) * VV + u0];
    float o0 = ov.x * L2E, o1 = ov.y * L2E;

#pragma unroll 1
    for (int si = 0; si < NSEQ - 1; si++) {
        const uint32_t p = (uint32_t)(si & 1);
        if (si) {
            mbar_wait(mb0 + 8 * p, (uint32_t)(((si - 1) >> 1) & 1));
            if (tid == 0) mbar_expect(mb0 + 8 * p, 2048);
        }
        const float* cbuf = sh + p * 512;
        float* ebuf = eb + p * 512;
        const float offc = cbuf[1];
        ebuf[tid] = ex2f_(cbuf[tid] - offc);
        __syncthreads();

        const ulonglong2* ep = (const ulonglong2*)ebuf;
        ulonglong2 A = ep[lane], B = ep[lane + 32], C = ep[lane + 64], D = ep[lane + 96];
        uint64_t p0=0,p1=0,q0=0,q1=0;
        p0=fma2(A.x,e0p[0],p0); p1=fma2(A.y,e0p[1],p1);
        q0=fma2(A.x,e1p[0],q0); q1=fma2(A.y,e1p[1],q1);
        p0=fma2(B.x,e0p[2],p0); p1=fma2(B.y,e0p[3],p1);
        q0=fma2(B.x,e1p[2],q0); q1=fma2(B.y,e1p[3],q1);
        p0=fma2(C.x,e0p[4],p0); p1=fma2(C.y,e0p[5],p1);
        q0=fma2(C.x,e1p[4],q0); q1=fma2(C.y,e1p[5],q1);
        p0=fma2(D.x,e0p[6],p0); p1=fma2(D.y,e0p[7],p1);
        q0=fma2(D.x,e1p[6],q0); q1=fma2(D.y,e1p[7],q1);
        float s0 = wsum(sum2(p0) + sum2(p1));
        float s1 = wsum(sum2(q0) + sum2(q1));
        float cl0 = o0 + offc + lg2f_(s0);
        float cl1 = o1 + offc + lg2f_(s1);

        if (si == NSEQ - 2) {
            if (rank == 0 && tid == 0) out[0] = cl0 * LN2;
        } else {
            const uint32_t np = (uint32_t)((si + 1) & 1);
            if (lane < CL) st_async64(rA + np * 2048u, pack2(cl0, cl1), rM + 8u * np);
            int row = NSEQ - 3 - si;
            float2 onx = *(const float2*)&O[(size_t)row * VV + u0];
            o0 = onx.x * L2E; o1 = onx.y * L2E;
        }
    }
    cl_sync();
}

extern "C" void kernel_launch(void* const* d_in, const int* in_sizes, int n_in,
                              void* d_out, int out_size)
{
    const void*  nums = d_in[0];
    const float* emb  = (const float*)d_in[1];
    const float* Wxh1 = (const float*)d_in[2];
    const float* Whh1 = (const float*)d_in[3];
    const float* b1   = (const float*)d_in[4];
    const float* Wxh2 = (const float*)d_in[5];
    const float* Whh2 = (const float*)d_in[6];
    const float* b2   = (const float*)d_in[7];
    const float* Wl   = (const float*)d_in[8];
    const float* bl   = (const float*)d_in[9];
    const float* Tm   = (const float*)d_in[10];
    float* out = (float*)d_out;

    float *X, *XW, *H, *O;
    cudaGetSymbolAddress((void**)&X,  g_X);
    cudaGetSymbolAddress((void**)&XW, g_XW);
    cudaGetSymbolAddress((void**)&H,  g_H);
    cudaGetSymbolAddress((void**)&O,  g_O);

    cudaFuncSetAttribute((const void*)rnn_fused2, cudaFuncAttributeNonPortableClusterSizeAllowed, 1);
    cudaFuncSetAttribute((const void*)crf16,      cudaFuncAttributeNonPortableClusterSizeAllowed, 1);

    detect_kernel<<<1, 256>>>((const int*)nums);
    gather_kernel<<<NSEQ, 128>>>(nums, emb);
    expT_kernel<<<VV * VV / 256, 256>>>(Tm);

    dim3 gg(512 / 64, NSEQ / 64);
    gemm_bias<<<gg, 256>>>(X, Wxh1, b1, XW);      // XW1 = X@Wxh1 + b1

    cudaLaunchConfig_t cfg = {};
    cfg.gridDim  = dim3(CL, 1, 1);
    cfg.blockDim = dim3(512, 1, 1);
    cfg.dynamicSmemBytes = 0;
    cfg.stream = 0;
    cudaLaunchAttribute at[1];
    at[0].id = cudaLaunchAttributeClusterDimension;
    at[0].val.clusterDim.x = CL;
    at[0].val.clusterDim.y = 1;
    at[0].val.clusterDim.z = 1;
    cfg.attrs = at;
    cfg.numAttrs = 1;

    cudaLaunchKernelEx(&cfg, rnn_fused2, Whh1, (const float*)XW, Whh2, Wxh2, b2, H);
    gemm_bias<<<gg, 256>>>(H, Wl, bl, O);         // O = H@Wl + bl
    cudaLaunchKernelEx(&cfg, crf16, out);         // c0[BOS]
}

// round 10
// speedup vs baseline: 1.2192x; 1.0770x over previous
#include <cuda_runtime.h>
#include <cstdint>

#define NSEQ 2048
#define DD 512
#define VV 512
#define CL 16

static __device__ float g_X [NSEQ * DD];
static __device__ float g_XW[NSEQ * DD];
static __device__ float g_H2[NSEQ * DD];
static __device__ float g_O [NSEQ * VV];
static __device__ float g_E [VV * VV];
static __device__ int   g_hflag[NSEQ];
static __device__ int   g_oflag[NSEQ];
static __device__ int   g_is64;

__device__ __forceinline__ uint32_t ctarank() {
    uint32_t r; asm("mov.u32 %0, %%cluster_ctarank;" : "=r"(r)); return r;
}
__device__ __forceinline__ uint32_t s2u(const void* p) {
    uint32_t a;
    asm("{ .reg .u64 t; cvta.to.shared.u64 t, %1; cvt.u32.u64 %0, t; }" : "=r"(a) : "l"(p));
    return a;
}
__device__ __forceinline__ uint32_t mapa_(uint32_t laddr, uint32_t r) {
    uint32_t a; asm("mapa.shared::cluster.u32 %0, %1, %2;" : "=r"(a) : "r"(laddr), "r"(r));
    return a;
}
__device__ __forceinline__ void st_async64(uint32_t raddr, uint64_t v, uint32_t rmbar) {
    asm volatile("st.async.shared::cluster.mbarrier::complete_tx::bytes.b64 [%0], %1, [%2];"
                 :: "r"(raddr), "l"(v), "r"(rmbar) : "memory");
}
__device__ __forceinline__ void mbar_init(uint32_t mb, uint32_t cnt) {
    asm volatile("mbarrier.init.shared.b64 [%0], %1;" :: "r"(mb), "r"(cnt) : "memory");
}
__device__ __forceinline__ void mbar_expect(uint32_t mb, uint32_t bytes) {
    asm volatile("mbarrier.arrive.expect_tx.shared.b64 _, [%0], %1;" :: "r"(mb), "r"(bytes) : "memory");
}
__device__ __forceinline__ void mbar_wait(uint32_t mb, uint32_t parity) {
    asm volatile(
        "{\n\t.reg .pred P;\n"
        "W%=:\n\t"
        "mbarrier.try_wait.parity.acquire.cluster.shared::cta.b64 P, [%0], %1, 0x989680;\n\t"
        "@!P bra W%=;\n\t}"
        :: "r"(mb), "r"(parity) : "memory");
}
__device__ __forceinline__ void cl_sync() {
    asm volatile("barrier.cluster.arrive.aligned;" ::: "memory");
    asm volatile("barrier.cluster.wait.aligned;"   ::: "memory");
}
__device__ __forceinline__ int ld_acq(const int* p) {
    int v; asm volatile("ld.acquire.gpu.global.b32 %0, [%1];" : "=r"(v) : "l"(p) : "memory");
    return v;
}
__device__ __forceinline__ void st_rel(int* p, int v) {
    asm volatile("st.release.gpu.global.b32 [%0], %1;" :: "l"(p), "r"(v) : "memory");
}
__device__ __forceinline__ void wait_flag(const int* p) {
    while (ld_acq(p) == 0) { asm volatile("nanosleep.u32 128;"); }
}
__device__ __forceinline__ float wsum(float x) {
#pragma unroll
    for (int o = 16; o; o >>= 1) x += __shfl_xor_sync(0xffffffffu, x, o);
    return x;
}
__device__ __forceinline__ float ex2f_(float x) {
    float y; asm("ex2.approx.f32 %0, %1;" : "=f"(y) : "f"(x)); return y;
}
__device__ __forceinline__ float lg2f_(float x) {
    float y; asm("lg2.approx.f32 %0, %1;" : "=f"(y) : "f"(x)); return y;
}
__device__ __forceinline__ float rcpf_(float x) {
    float y; asm("rcp.approx.f32 %0, %1;" : "=f"(y) : "f"(x)); return y;
}
__device__ __forceinline__ float tanh_ex2(float x) {
    float t = ex2f_(2.8853900817779268f * x);
    float r = rcpf_(t + 1.0f);
    return fmaf(-2.0f, r, 1.0f);
}
__device__ __forceinline__ uint64_t pack2(float a, float b) {
    uint64_t d; asm("mov.b64 %0, {%1, %2};" : "=l"(d) : "f"(a), "f"(b)); return d;
}
__device__ __forceinline__ uint64_t fma2(uint64_t a, uint64_t b, uint64_t c) {
    uint64_t d; asm("fma.rn.f32x2 %0, %1, %2, %3;" : "=l"(d) : "l"(a), "l"(b), "l"(c));
    return d;
}
__device__ __forceinline__ float sum2(uint64_t v) {
    float lo, hi; asm("mov.b64 {%0, %1}, %2;" : "=f"(lo), "=f"(hi) : "l"(v));
    return lo + hi;
}

__global__ void detect_kernel(const int* __restrict__ w) {
    __shared__ int any;
    if (threadIdx.x == 0) any = 0;
    __syncthreads();
    int acc = 0;
    for (int i = threadIdx.x; i < NSEQ / 2; i += blockDim.x) acc |= w[2 * i + 1];
    if (acc) atomicOr(&any, 1);
    __syncthreads();
    if (threadIdx.x == 0) g_is64 = (any == 0) ? 1 : 0;
}
__global__ void gather_kernel(const void* __restrict__ nums, const float* __restrict__ emb) {
    int t = blockIdx.x;
    long long idx = g_is64 ? ((const long long*)nums)[t]
                           : (long long)((const int*)nums)[t];
    const float4* src = (const float4*)(emb + (size_t)idx * DD);
    float4* dst = (float4*)(&g_X[(size_t)t * DD]);
    dst[threadIdx.x] = src[threadIdx.x];
}
__global__ void expT_kernel(const float* __restrict__ T) {
    int i = blockIdx.x * 256 + threadIdx.x;
    g_E[i] = ex2f_(T[i] * 1.4426950408889634f);
}
__global__ void zero_flags_kernel() {
    int i = blockIdx.x * 256 + threadIdx.x;
    g_hflag[i] = 0; g_oflag[i] = 0;
}

__global__ __launch_bounds__(256)
void gemm_bias(const float* __restrict__ A, const float* __restrict__ B,
               const float* __restrict__ bias, float* __restrict__ C)
{
    __shared__ __align__(16) float As[16][68];
    __shared__ __align__(16) float Bs[16][68];
    const int tid = threadIdx.x;
    const int bm = blockIdx.y * 64, bn = blockIdx.x * 64;
    const int tm = tid >> 4, tn = tid & 15;
    float acc[4][4] = {};
    for (int k0 = 0; k0 < 512; k0 += 16) {
        {
            int row = tid >> 2, cg = (tid & 3) * 4;
            float4 v = *(const float4*)(A + (size_t)(bm + row) * 512 + k0 + cg);
            As[cg + 0][row] = v.x; As[cg + 1][row] = v.y;
            As[cg + 2][row] = v.z; As[cg + 3][row] = v.w;
        }
        {
            int row = tid >> 4, col = (tid & 15) * 4;
            *(float4*)&Bs[row][col] = *(const float4*)(B + (size_t)(k0 + row) * 512 + bn + col);
        }
        __syncthreads();
#pragma unroll
        for (int k = 0; k < 16; k++) {
            float4 a = *(const float4*)&As[k][tm * 4];
            float4 b = *(const float4*)&Bs[k][tn * 4];
            float av[4] = {a.x, a.y, a.z, a.w};
            float bv[4] = {b.x, b.y, b.z, b.w};
#pragma unroll
            for (int i = 0; i < 4; i++)
#pragma unroll
                for (int jj = 0; jj < 4; jj++)
                    acc[i][jj] = fmaf(av[i], bv[jj], acc[i][jj]);
        }
        __syncthreads();
    }
    float4 bb = *(const float4*)(bias + bn + tn * 4);
#pragma unroll
    for (int i = 0; i < 4; i++) {
        float4 o;
        o.x = acc[i][0] + bb.x; o.y = acc[i][1] + bb.y;
        o.z = acc[i][2] + bb.z; o.w = acc[i][3] + bb.w;
        *(float4*)(C + (size_t)(bm + tm * 4 + i) * 512 + bn + tn * 4) = o;
    }
}

// ===== mega kernel: 48 CTAs = cluster0 (RNN) + cluster1 (alpha) + 16 builders =====
__global__ void __launch_bounds__(512, 1)
mega(const float* __restrict__ Whh1, const float* __restrict__ XW1,
     const float* __restrict__ Whh2, const float* __restrict__ Wxh2,
     const float* __restrict__ b2,   const float* __restrict__ Wl,
     const float* __restrict__ bl,   float* __restrict__ out)
{
    __shared__ __align__(16) float sh1[2 * 512];
    __shared__ __align__(16) float sh2[2 * 512];
    __shared__ __align__(8) long long mbar[4];
    const int bid  = blockIdx.x;
    const int tid  = threadIdx.x;
    const int lane = tid & 31;
    const int w    = tid >> 5;
    const float L2E = 1.4426950408889634f;
    const float LN2 = 0.6931471805599453f;

    if (bid < 16) {
        // ---------------- role A: fused 2-layer RNN ----------------
        const uint32_t rank = ctarank();
        const int j0 = (int)rank * 32 + 2 * w;
        uint64_t w1a[8], w1b[8], xa[8], xb[8], ha[8], hb[8];
#pragma unroll
        for (int i = 0; i < 4; i++)
#pragma unroll
            for (int j = 0; j < 2; j++) {
                int k = 128 * i + 4 * lane + 2 * j;
                w1a[2*i+j] = pack2(Whh1[(size_t)k*DD + j0],   Whh1[(size_t)(k+1)*DD + j0]);
                w1b[2*i+j] = pack2(Whh1[(size_t)k*DD + j0+1], Whh1[(size_t)(k+1)*DD + j0+1]);
                xa [2*i+j] = pack2(Wxh2[(size_t)k*DD + j0],   Wxh2[(size_t)(k+1)*DD + j0]);
                xb [2*i+j] = pack2(Wxh2[(size_t)k*DD + j0+1], Wxh2[(size_t)(k+1)*DD + j0+1]);
                ha [2*i+j] = pack2(Whh2[(size_t)k*DD + j0],   Whh2[(size_t)(k+1)*DD + j0]);
                hb [2*i+j] = pack2(Whh2[(size_t)k*DD + j0+1], Whh2[(size_t)(k+1)*DD + j0+1]);
            }
        const float bj0 = b2[j0], bj1 = b2[j0 + 1];
        for (int i = tid; i < 2 * 512; i += 512) { sh1[i] = 0.0f; sh2[i] = 0.0f; }
        const uint32_t b1 = s2u(sh1), b2s = s2u(sh2), mb = s2u(mbar);
        if (tid == 0) {
#pragma unroll
            for (int q = 0; q < 4; q++) mbar_init(mb + 8*q, 1);
#pragma unroll
            for (int q = 0; q < 4; q++) mbar_expect(mb + 8*q, 2048);
        }
        __syncthreads();
        cl_sync();
        uint32_t rA1 = 0, rA2 = 0, rM = 0;
        if (lane < CL) {
            rA1 = mapa_(b1  + rank * 128u + 8u * (uint32_t)w, (uint32_t)lane);
            rA2 = mapa_(b2s + rank * 128u + 8u * (uint32_t)w, (uint32_t)lane);
            rM  = mapa_(mb, (uint32_t)lane);
        }
        float2 xw = *(const float2*)&XW1[j0];

#pragma unroll 1
        for (int r = 0; r <= NSEQ + 1; r++) {
            const uint32_t p = (uint32_t)(r & 1), np = (uint32_t)((r + 1) & 1);
            const uint32_t ph = (uint32_t)(((r - 1) >> 1) & 1);
            if (r >= 1 && r <= NSEQ) {
                mbar_wait(mb + 8 * p, ph);
                if (tid == 0) mbar_expect(mb + 8 * p, 2048);
            }
            uint64_t u0_=0, u1_=0, v0_=0, v1_=0;
            if (r <= NSEQ) {
                const ulonglong2* c1 = (const ulonglong2*)(sh1 + p * 512);
                ulonglong2 A = c1[lane], B = c1[lane + 32], C = c1[lane + 64], D = c1[lane + 96];
                if (r < NSEQ) {
                    uint64_t p0=0,p1=0,q0=0,q1=0;
                    p0=fma2(A.x,w1a[0],p0); p1=fma2(A.y,w1a[1],p1);
                    q0=fma2(A.x,w1b[0],q0); q1=fma2(A.y,w1b[1],q1);
                    p0=fma2(B.x,w1a[2],p0); p1=fma2(B.y,w1a[3],p1);
                    q0=fma2(B.x,w1b[2],q0); q1=fma2(B.y,w1b[3],q1);
                    p0=fma2(C.x,w1a[4],p0); p1=fma2(C.y,w1a[5],p1);
                    q0=fma2(C.x,w1b[4],q0); q1=fma2(C.y,w1b[5],q1);
                    p0=fma2(D.x,w1a[6],p0); p1=fma2(D.y,w1a[7],p1);
                    q0=fma2(D.x,w1b[6],q0); q1=fma2(D.y,w1b[7],q1);
                    float ps = wsum(sum2(p0) + sum2(p1));
                    float qs = wsum(sum2(q0) + sum2(q1));
                    float a0 = tanh_ex2(xw.x + ps);
                    float a1 = tanh_ex2(xw.y + qs);
                    if (lane < CL) st_async64(rA1 + np * 2048u, pack2(a0, a1), rM + 8u * np);
                }
                u0_=fma2(A.x,xa[0],u0_); u1_=fma2(A.y,xa[1],u1_);
                v0_=fma2(A.x,xb[0],v0_); v1_=fma2(A.y,xb[1],v1_);
                u0_=fma2(B.x,xa[2],u0_); u1_=fma2(B.y,xa[3],u1_);
                v0_=fma2(B.x,xb[2],v0_); v1_=fma2(B.y,xb[3],v1_);
                u0_=fma2(C.x,xa[4],u0_); u1_=fma2(C.y,xa[5],u1_);
                v0_=fma2(C.x,xb[4],v0_); v1_=fma2(C.y,xb[5],v1_);
                u0_=fma2(D.x,xa[6],u0_); u1_=fma2(D.y,xa[7],u1_);
                v0_=fma2(D.x,xb[6],v0_); v1_=fma2(D.y,xb[7],v1_);
            }
            if (r >= 1) {
                mbar_wait(mb + 16 + 8 * p, ph);
                if (tid == 0) mbar_expect(mb + 16 + 8 * p, 2048);
                if (r >= 2) {                 // publish row r-2 (this CTA holds full row)
                    int row = r - 2;
                    if ((int)rank == (row & 15)) {
                        g_H2[(size_t)row * DD + tid] = sh2[p * 512 + tid];
                        __syncthreads();
                        if (tid == 0) st_rel(&g_hflag[row], 1);
                    }
                }
                if (r <= NSEQ) {
                    const ulonglong2* c2 = (const ulonglong2*)(sh2 + p * 512);
                    ulonglong2 E = c2[lane], F = c2[lane + 32], G = c2[lane + 64], H = c2[lane + 96];
                    u0_=fma2(E.x,ha[0],u0_); u1_=fma2(E.y,ha[1],u1_);
                    v0_=fma2(E.x,hb[0],v0_); v1_=fma2(E.y,hb[1],v1_);
                    u0_=fma2(F.x,ha[2],u0_); u1_=fma2(F.y,ha[3],u1_);
                    v0_=fma2(F.x,hb[2],v0_); v1_=fma2(F.y,hb[3],v1_);
                    u0_=fma2(G.x,ha[4],u0_); u1_=fma2(G.y,ha[5],u1_);
                    v0_=fma2(G.x,hb[4],v0_); v1_=fma2(G.y,hb[5],v1_);
                    u0_=fma2(H.x,ha[6],u0_); u1_=fma2(H.y,ha[7],u1_);
                    v0_=fma2(H.x,hb[6],v0_); v1_=fma2(H.y,hb[7],v1_);
                    float us = wsum(sum2(u0_) + sum2(u1_));
                    float vs = wsum(sum2(v0_) + sum2(v1_));
                    float h0 = tanh_ex2(us + bj0);
                    float h1 = tanh_ex2(vs + bj1);
                    if (lane < CL)
                        st_async64(rA2 + np * 2048u, pack2(h0, h1), rM + 16u + 8u * np);
                }
            } else {
                if (lane < CL) st_async64(rA2 + np * 2048u, 0ull, rM + 16u + 8u * np);
            }
            if (r + 1 < NSEQ) xw = *(const float2*)&XW1[(size_t)(r + 1) * DD + j0];
        }
        cl_sync();
    } else if (bid < 32) {
        // ---------------- role B: forward CRF (alpha) ----------------
        const uint32_t rank = ctarank();
        const int u0 = (int)rank * 32 + 2 * w;       // output labels v = u0, u0+1
        uint64_t e0p[8], e1p[8];
#pragma unroll
        for (int i = 0; i < 4; i++)
#pragma unroll
            for (int j = 0; j < 2; j++) {
                int k = 128 * i + 4 * lane + 2 * j;   // source label u
                e0p[2*i+j] = pack2(g_E[(size_t)k*VV + u0],     g_E[(size_t)(k+1)*VV + u0]);
                e1p[2*i+j] = pack2(g_E[(size_t)k*VV + u0 + 1], g_E[(size_t)(k+1)*VV + u0 + 1]);
            }
        for (int i = tid; i < 2 * 512; i += 512) sh1[i] = -1.0e30f;
        const uint32_t b1 = s2u(sh1), mb = s2u(mbar);
        if (tid == 0) {
            mbar_init(mb, 1);      mbar_init(mb + 8, 1);
            mbar_expect(mb, 2048); mbar_expect(mb + 8, 2048);
            wait_flag(&g_oflag[0]);
            sh1[0] = g_O[0] * L2E;                    // a0[BOS] = O[0][BOS]
        }
        __syncthreads();
        cl_sync();
        uint32_t rA = 0, rM = 0;
        if (lane < CL) {
            rA = mapa_(b1 + rank * 128u + 8u * (uint32_t)w, (uint32_t)lane);
            rM = mapa_(mb, (uint32_t)lane);
        }
        wait_flag(&g_oflag[1]);
        float2 ov = *(const float2*)&g_O[(size_t)VV + u0];
        float o0 = ov.x * L2E, o1 = ov.y * L2E;

#pragma unroll 1
        for (int si = 0; si < NSEQ - 1; si++) {
            const uint32_t p = (uint32_t)(si & 1);
            if (si) {
                mbar_wait(mb + 8 * p, (uint32_t)(((si - 1) >> 1) & 1));
                if (tid == 0) mbar_expect(mb + 8 * p, 2048);
            }
            const float* cbuf = sh1 + p * 512;
            const float offc = cbuf[0];               // a[BOS] as offset
            sh2[p * 512 + tid] = ex2f_(cbuf[tid] - offc);
            __syncthreads();
            const ulonglong2* ep = (const ulonglong2*)(sh2 + p * 512);
            ulonglong2 A = ep[lane], B = ep[lane + 32], C = ep[lane + 64], D = ep[lane + 96];
            uint64_t p0=0,p1=0,q0=0,q1=0;
            p0=fma2(A.x,e0p[0],p0); p1=fma2(A.y,e0p[1],p1);
            q0=fma2(A.x,e1p[0],q0); q1=fma2(A.y,e1p[1],q1);
            p0=fma2(B.x,e0p[2],p0); p1=fma2(B.y,e0p[3],p1);
            q0=fma2(B.x,e1p[2],q0); q1=fma2(B.y,e1p[3],q1);
            p0=fma2(C.x,e0p[4],p0); p1=fma2(C.y,e0p[5],p1);
            q0=fma2(C.x,e1p[4],q0); q1=fma2(C.y,e1p[5],q1);
            p0=fma2(D.x,e0p[6],p0); p1=fma2(D.y,e0p[7],p1);
            q0=fma2(D.x,e1p[6],q0); q1=fma2(D.y,e1p[7],q1);
            float s0 = wsum(sum2(p0) + sum2(p1));
            float s1 = wsum(sum2(q0) + sum2(q1));
            float al0 = o0 + offc + lg2f_(s0);
            float al1 = o1 + offc + lg2f_(s1);
            if (si == NSEQ - 2) {
                if (rank == 0 && tid == 0) out[0] = al1 * LN2;   // a_{n-1}[EOS], EOS=1
            } else {
                const uint32_t np = (uint32_t)((si + 1) & 1);
                if (lane < CL) st_async64(rA + np * 2048u, pack2(al0, al1), rM + 8u * np);
                int row = si + 2;
                wait_flag(&g_oflag[row]);
                float2 onx = *(const float2*)&g_O[(size_t)row * VV + u0];
                o0 = onx.x * L2E; o1 = onx.y * L2E;
            }
        }
        cl_sync();
    } else {
        // ---------------- role C: O-row builders ----------------
        const int b = bid - 32;       // 0..15
        for (int row = b; row < NSEQ; row += 16) {
            wait_flag(&g_hflag[row]);
            sh1[tid] = g_H2[(size_t)row * DD + tid];
            __syncthreads();
            float acc = bl[tid];
            const float* wc = Wl + tid;
#pragma unroll 8
            for (int k = 0; k < DD; k++) acc = fmaf(sh1[k], wc[(size_t)k * VV], acc);
            g_O[(size_t)row * VV + tid] = acc;
            __syncthreads();
            if (tid == 0) st_rel(&g_oflag[row], 1);
        }
    }
}

extern "C" void kernel_launch(void* const* d_in, const int* in_sizes, int n_in,
                              void* d_out, int out_size)
{
    const void*  nums = d_in[0];
    const float* emb  = (const float*)d_in[1];
    const float* Wxh1 = (const float*)d_in[2];
    const float* Whh1 = (const float*)d_in[3];
    const float* b1   = (const float*)d_in[4];
    const float* Wxh2 = (const float*)d_in[5];
    const float* Whh2 = (const float*)d_in[6];
    const float* b2   = (const float*)d_in[7];
    const float* Wl   = (const float*)d_in[8];
    const float* bl   = (const float*)d_in[9];
    const float* Tm   = (const float*)d_in[10];
    float* out = (float*)d_out;

    float *X, *XW;
    cudaGetSymbolAddress((void**)&X,  g_X);
    cudaGetSymbolAddress((void**)&XW, g_XW);

    cudaFuncSetAttribute((const void*)mega, cudaFuncAttributeNonPortableClusterSizeAllowed, 1);

    detect_kernel<<<1, 256>>>((const int*)nums);
    gather_kernel<<<NSEQ, 128>>>(nums, emb);
    expT_kernel<<<VV * VV / 256, 256>>>(Tm);
    zero_flags_kernel<<<NSEQ / 256, 256>>>();

    dim3 gg(512 / 64, NSEQ / 64);
    gemm_bias<<<gg, 256>>>(X, Wxh1, b1, XW);      // XW1 = X@Wxh1 + b1

    cudaLaunchConfig_t cfg = {};
    cfg.gridDim  = dim3(48, 1, 1);                // 3 clusters of 16
    cfg.blockDim = dim3(512, 1, 1);
    cfg.dynamicSmemBytes = 0;
    cfg.stream = 0;
    cudaLaunchAttribute at[1];
    at[0].id = cudaLaunchAttributeClusterDimension;
    at[0].val.clusterDim.x = CL;
    at[0].val.clusterDim.y = 1;
    at[0].val.clusterDim.z = 1;
    cfg.attrs = at;
    cfg.numAttrs = 1;

    cudaLaunchKernelEx(&cfg, mega, Whh1, (const float*)XW, Whh2, Wxh2, b2, Wl, bl, out);
}

// round 11
// speedup vs baseline: 1.7557x; 1.4400x over previous
#include <cuda_runtime.h>
#include <cstdint>

#define NSEQ 2048
#define DD 512
#define VV 512
#define CL 16

static __device__ float g_X [NSEQ * DD];
static __device__ float g_XW[NSEQ * DD];
static __device__ float g_H2[NSEQ * DD];
static __device__ float g_O [NSEQ * VV];
static __device__ float g_E [VV * VV];
static __device__ int   g_hflag[NSEQ];
static __device__ int   g_oflag[NSEQ];
static __device__ int   g_is64;

__device__ __forceinline__ uint32_t ctarank() {
    uint32_t r; asm("mov.u32 %0, %%cluster_ctarank;" : "=r"(r)); return r;
}
__device__ __forceinline__ uint32_t s2u(const void* p) {
    uint32_t a;
    asm("{ .reg .u64 t; cvta.to.shared.u64 t, %1; cvt.u32.u64 %0, t; }" : "=r"(a) : "l"(p));
    return a;
}
__device__ __forceinline__ uint32_t mapa_(uint32_t laddr, uint32_t r) {
    uint32_t a; asm("mapa.shared::cluster.u32 %0, %1, %2;" : "=r"(a) : "r"(laddr), "r"(r));
    return a;
}
__device__ __forceinline__ void st_async64(uint32_t raddr, uint64_t v, uint32_t rmbar) {
    asm volatile("st.async.shared::cluster.mbarrier::complete_tx::bytes.b64 [%0], %1, [%2];"
                 :: "r"(raddr), "l"(v), "r"(rmbar) : "memory");
}
__device__ __forceinline__ void mbar_init(uint32_t mb, uint32_t cnt) {
    asm volatile("mbarrier.init.shared.b64 [%0], %1;" :: "r"(mb), "r"(cnt) : "memory");
}
__device__ __forceinline__ void mbar_expect(uint32_t mb, uint32_t bytes) {
    asm volatile("mbarrier.arrive.expect_tx.shared.b64 _, [%0], %1;" :: "r"(mb), "r"(bytes) : "memory");
}
__device__ __forceinline__ void mbar_wait(uint32_t mb, uint32_t parity) {
    asm volatile(
        "{\n\t.reg .pred P;\n"
        "W%=:\n\t"
        "mbarrier.try_wait.parity.acquire.cluster.shared::cta.b64 P, [%0], %1, 0x989680;\n\t"
        "@!P bra W%=;\n\t}"
        :: "r"(mb), "r"(parity) : "memory");
}
__device__ __forceinline__ void cl_sync() {
    asm volatile("barrier.cluster.arrive.aligned;" ::: "memory");
    asm volatile("barrier.cluster.wait.aligned;"   ::: "memory");
}
__device__ __forceinline__ int ld_acq(const int* p) {
    int v; asm volatile("ld.acquire.gpu.global.b32 %0, [%1];" : "=r"(v) : "l"(p) : "memory");
    return v;
}
__device__ __forceinline__ void st_rel(int* p, int v) {
    asm volatile("st.release.gpu.global.b32 [%0], %1;" :: "l"(p), "r"(v) : "memory");
}
__device__ __forceinline__ void wait_flag(const int* p) {
    while (ld_acq(p) == 0) { asm volatile("nanosleep.u32 128;"); }
}
__device__ __forceinline__ float wsum(float x) {
#pragma unroll
    for (int o = 16; o; o >>= 1) x += __shfl_xor_sync(0xffffffffu, x, o);
    return x;
}
__device__ __forceinline__ float ex2f_(float x) {
    float y; asm("ex2.approx.f32 %0, %1;" : "=f"(y) : "f"(x)); return y;
}
__device__ __forceinline__ float lg2f_(float x) {
    float y; asm("lg2.approx.f32 %0, %1;" : "=f"(y) : "f"(x)); return y;
}
__device__ __forceinline__ float rcpf_(float x) {
    float y; asm("rcp.approx.f32 %0, %1;" : "=f"(y) : "f"(x)); return y;
}
__device__ __forceinline__ float tanh_ex2(float x) {
    float t = ex2f_(2.8853900817779268f * x);
    float r = rcpf_(t + 1.0f);
    return fmaf(-2.0f, r, 1.0f);
}
__device__ __forceinline__ uint64_t pack2(float a, float b) {
    uint64_t d; asm("mov.b64 %0, {%1, %2};" : "=l"(d) : "f"(a), "f"(b)); return d;
}
__device__ __forceinline__ uint64_t fma2(uint64_t a, uint64_t b, uint64_t c) {
    uint64_t d; asm("fma.rn.f32x2 %0, %1, %2, %3;" : "=l"(d) : "l"(a), "l"(b), "l"(c));
    return d;
}
__device__ __forceinline__ float sum2(uint64_t v) {
    float lo, hi; asm("mov.b64 {%0, %1}, %2;" : "=f"(lo), "=f"(hi) : "l"(v));
    return lo + hi;
}

__global__ void detect_kernel(const int* __restrict__ w) {
    __shared__ int any;
    if (threadIdx.x == 0) any = 0;
    __syncthreads();
    int acc = 0;
    for (int i = threadIdx.x; i < NSEQ / 2; i += blockDim.x) acc |= w[2 * i + 1];
    if (acc) atomicOr(&any, 1);
    __syncthreads();
    if (threadIdx.x == 0) g_is64 = (any == 0) ? 1 : 0;
}
__global__ void gather_kernel(const void* __restrict__ nums, const float* __restrict__ emb) {
    int t = blockIdx.x;
    long long idx = g_is64 ? ((const long long*)nums)[t]
                           : (long long)((const int*)nums)[t];
    const float4* src = (const float4*)(emb + (size_t)idx * DD);
    float4* dst = (float4*)(&g_X[(size_t)t * DD]);
    dst[threadIdx.x] = src[threadIdx.x];
}
__global__ void expT_kernel(const float* __restrict__ T) {
    int i = blockIdx.x * 256 + threadIdx.x;
    g_E[i] = ex2f_(T[i] * 1.4426950408889634f);
}
__global__ void zero_flags_kernel() {
    int i = blockIdx.x * 256 + threadIdx.x;
    g_hflag[i] = 0; g_oflag[i] = 0;
}

__global__ __launch_bounds__(256)
void gemm_bias(const float* __restrict__ A, const float* __restrict__ B,
               const float* __restrict__ bias, float* __restrict__ C)
{
    __shared__ __align__(16) float As[16][68];
    __shared__ __align__(16) float Bs[16][68];
    const int tid = threadIdx.x;
    const int bm = blockIdx.y * 64, bn = blockIdx.x * 64;
    const int tm = tid >> 4, tn = tid & 15;
    float acc[4][4] = {};
    for (int k0 = 0; k0 < 512; k0 += 16) {
        {
            int row = tid >> 2, cg = (tid & 3) * 4;
            float4 v = *(const float4*)(A + (size_t)(bm + row) * 512 + k0 + cg);
            As[cg + 0][row] = v.x; As[cg + 1][row] = v.y;
            As[cg + 2][row] = v.z; As[cg + 3][row] = v.w;
        }
        {
            int row = tid >> 4, col = (tid & 15) * 4;
            *(float4*)&Bs[row][col] = *(const float4*)(B + (size_t)(k0 + row) * 512 + bn + col);
        }
        __syncthreads();
#pragma unroll
        for (int k = 0; k < 16; k++) {
            float4 a = *(const float4*)&As[k][tm * 4];
            float4 b = *(const float4*)&Bs[k][tn * 4];
            float av[4] = {a.x, a.y, a.z, a.w};
            float bv[4] = {b.x, b.y, b.z, b.w};
#pragma unroll
            for (int i = 0; i < 4; i++)
#pragma unroll
                for (int jj = 0; jj < 4; jj++)
                    acc[i][jj] = fmaf(av[i], bv[jj], acc[i][jj]);
        }
        __syncthreads();
    }
    float4 bb = *(const float4*)(bias + bn + tn * 4);
#pragma unroll
    for (int i = 0; i < 4; i++) {
        float4 o;
        o.x = acc[i][0] + bb.x; o.y = acc[i][1] + bb.y;
        o.z = acc[i][2] + bb.z; o.w = acc[i][3] + bb.w;
        *(float4*)(C + (size_t)(bm + tm * 4 + i) * 512 + bn + tn * 4) = o;
    }
}

// ===== mega kernel: 48 CTAs = cluster0 (RNN) + cluster1 (alpha) + 16 builders =====
__global__ void __launch_bounds__(512, 1)
mega(const float* __restrict__ Whh1, const float* __restrict__ XW1,
     const float* __restrict__ Whh2, const float* __restrict__ Wxh2,
     const float* __restrict__ b2,   const float* __restrict__ Wl,
     const float* __restrict__ bl,   float* __restrict__ out)
{
    __shared__ __align__(16) float sh1[2 * 512];
    __shared__ __align__(16) float sh2[2 * 512];
    __shared__ __align__(8) long long mbar[2];
    const int bid  = blockIdx.x;
    const int tid  = threadIdx.x;
    const int lane = tid & 31;
    const int w    = tid >> 5;
    const float L2E = 1.4426950408889634f;
    const float LN2 = 0.6931471805599453f;

    if (bid < 16) {
        // ---------------- role A: fused 2-layer RNN, ONE barrier/round ----------------
        const uint32_t rank = ctarank();
        const int j0 = (int)rank * 32 + 2 * w;
        uint64_t w1a[8], w1b[8], xa[8], xb[8], ha[8], hb[8];
#pragma unroll
        for (int i = 0; i < 4; i++)
#pragma unroll
            for (int j = 0; j < 2; j++) {
                int k = 128 * i + 4 * lane + 2 * j;
                w1a[2*i+j] = pack2(Whh1[(size_t)k*DD + j0],   Whh1[(size_t)(k+1)*DD + j0]);
                w1b[2*i+j] = pack2(Whh1[(size_t)k*DD + j0+1], Whh1[(size_t)(k+1)*DD + j0+1]);
                xa [2*i+j] = pack2(Wxh2[(size_t)k*DD + j0],   Wxh2[(size_t)(k+1)*DD + j0]);
                xb [2*i+j] = pack2(Wxh2[(size_t)k*DD + j0+1], Wxh2[(size_t)(k+1)*DD + j0+1]);
                ha [2*i+j] = pack2(Whh2[(size_t)k*DD + j0],   Whh2[(size_t)(k+1)*DD + j0]);
                hb [2*i+j] = pack2(Whh2[(size_t)k*DD + j0+1], Whh2[(size_t)(k+1)*DD + j0+1]);
            }
        const float bj0 = b2[j0], bj1 = b2[j0 + 1];
        for (int i = tid; i < 2 * 512; i += 512) { sh1[i] = 0.0f; sh2[i] = 0.0f; }
        const uint32_t b1 = s2u(sh1), b2s = s2u(sh2), mb = s2u(mbar);
        if (tid == 0) {
            mbar_init(mb, 1);      mbar_init(mb + 8, 1);
            mbar_expect(mb, 4096); mbar_expect(mb + 8, 4096);
        }
        __syncthreads();
        cl_sync();
        uint32_t rA1 = 0, rA2 = 0, rM = 0;
        if (lane < CL) {
            rA1 = mapa_(b1  + rank * 128u + 8u * (uint32_t)w, (uint32_t)lane);
            rA2 = mapa_(b2s + rank * 128u + 8u * (uint32_t)w, (uint32_t)lane);
            rM  = mapa_(mb, (uint32_t)lane);
        }
        float2 xw = *(const float2*)&XW1[j0];

#pragma unroll 1
        for (int r = 0; r <= NSEQ + 1; r++) {
            const uint32_t p = (uint32_t)(r & 1), np = (uint32_t)((r + 1) & 1);
            if (r) {
                mbar_wait(mb + 8 * p, (uint32_t)(((r - 1) >> 1) & 1));
                if (tid == 0) mbar_expect(mb + 8 * p, 4096);
            }
            // snapshot publish row early (buffer stable until round r+2 messages)
            const bool ispub = (r >= 2) && ((int)rank == ((r - 2) & 15));
            float pub = 0.0f;
            if (ispub) pub = sh2[p * 512 + tid];

            if (r <= NSEQ) {
                const ulonglong2* c1 = (const ulonglong2*)(sh1 + p * 512);
                ulonglong2 A = c1[lane], B = c1[lane + 32], C = c1[lane + 64], D = c1[lane + 96];
                // h1 chain (critical): matvec + reduce + send ASAP
                if (r < NSEQ) {
                    uint64_t p0=0,p1=0,q0=0,q1=0;
                    p0=fma2(A.x,w1a[0],p0); p1=fma2(A.y,w1a[1],p1);
                    q0=fma2(A.x,w1b[0],q0); q1=fma2(A.y,w1b[1],q1);
                    p0=fma2(B.x,w1a[2],p0); p1=fma2(B.y,w1a[3],p1);
                    q0=fma2(B.x,w1b[2],q0); q1=fma2(B.y,w1b[3],q1);
                    p0=fma2(C.x,w1a[4],p0); p1=fma2(C.y,w1a[5],p1);
                    q0=fma2(C.x,w1b[4],q0); q1=fma2(C.y,w1b[5],q1);
                    p0=fma2(D.x,w1a[6],p0); p1=fma2(D.y,w1a[7],p1);
                    q0=fma2(D.x,w1b[6],q0); q1=fma2(D.y,w1b[7],q1);
                    float ps = wsum(sum2(p0) + sum2(p1));
                    float qs = wsum(sum2(q0) + sum2(q1));
                    float a0 = tanh_ex2(xw.x + ps);
                    float a1 = tanh_ex2(xw.y + qs);
                    if (lane < CL) st_async64(rA1 + np * 2048u, pack2(a0, a1), rM + 8u * np);
                } else {
                    if (lane < CL) st_async64(rA1 + np * 2048u, 0ull, rM + 8u * np);  // dummy keeps tx uniform
                }
                // h2 chain: x-matvec + h2-matvec (sh2[p] valid from the same wait)
                uint64_t u0_=0, u1_=0, v0_=0, v1_=0;
                u0_=fma2(A.x,xa[0],u0_); u1_=fma2(A.y,xa[1],u1_);
                v0_=fma2(A.x,xb[0],v0_); v1_=fma2(A.y,xb[1],v1_);
                u0_=fma2(B.x,xa[2],u0_); u1_=fma2(B.y,xa[3],u1_);
                v0_=fma2(B.x,xb[2],v0_); v1_=fma2(B.y,xb[3],v1_);
                u0_=fma2(C.x,xa[4],u0_); u1_=fma2(C.y,xa[5],u1_);
                v0_=fma2(C.x,xb[4],v0_); v1_=fma2(C.y,xb[5],v1_);
                u0_=fma2(D.x,xa[6],u0_); u1_=fma2(D.y,xa[7],u1_);
                v0_=fma2(D.x,xb[6],v0_); v1_=fma2(D.y,xb[7],v1_);
                const ulonglong2* c2 = (const ulonglong2*)(sh2 + p * 512);
                ulonglong2 E = c2[lane], F = c2[lane + 32], G = c2[lane + 64], H = c2[lane + 96];
                u0_=fma2(E.x,ha[0],u0_); u1_=fma2(E.y,ha[1],u1_);
                v0_=fma2(E.x,hb[0],v0_); v1_=fma2(E.y,hb[1],v1_);
                u0_=fma2(F.x,ha[2],u0_); u1_=fma2(F.y,ha[3],u1_);
                v0_=fma2(F.x,hb[2],v0_); v1_=fma2(F.y,hb[3],v1_);
                u0_=fma2(G.x,ha[4],u0_); u1_=fma2(G.y,ha[5],u1_);
                v0_=fma2(G.x,hb[4],v0_); v1_=fma2(G.y,hb[5],v1_);
                u0_=fma2(H.x,ha[6],u0_); u1_=fma2(H.y,ha[7],u1_);
                v0_=fma2(H.x,hb[6],v0_); v1_=fma2(H.y,hb[7],v1_);
                float us = wsum(sum2(u0_) + sum2(u1_));
                float vs = wsum(sum2(v0_) + sum2(v1_));
                float h0 = (r >= 1) ? tanh_ex2(us + bj0) : 0.0f;   // h2_{-1} = 0
                float h1 = (r >= 1) ? tanh_ex2(vs + bj1) : 0.0f;
                if (lane < CL) st_async64(rA2 + np * 2048u, pack2(h0, h1), rM + 8u * np);
            }
            // publish row r-2 AFTER sends (absorbed by next wait)
            if (ispub) {
                g_H2[(size_t)(r - 2) * DD + tid] = pub;
                __syncthreads();
                if (tid == 0) st_rel(&g_hflag[r - 2], 1);
            }
            if (r + 1 < NSEQ) xw = *(const float2*)&XW1[(size_t)(r + 1) * DD + j0];
        }
        cl_sync();
    } else if (bid < 32) {
        // ---------------- role B: forward CRF (alpha) ----------------
        const uint32_t rank = ctarank();
        const int u0 = (int)rank * 32 + 2 * w;       // output labels v = u0, u0+1
        uint64_t e0p[8], e1p[8];
#pragma unroll
        for (int i = 0; i < 4; i++)
#pragma unroll
            for (int j = 0; j < 2; j++) {
                int k = 128 * i + 4 * lane + 2 * j;   // source label u
                e0p[2*i+j] = pack2(g_E[(size_t)k*VV + u0],     g_E[(size_t)(k+1)*VV + u0]);
                e1p[2*i+j] = pack2(g_E[(size_t)k*VV + u0 + 1], g_E[(size_t)(k+1)*VV + u0 + 1]);
            }
        for (int i = tid; i < 2 * 512; i += 512) sh1[i] = -1.0e30f;
        const uint32_t b1 = s2u(sh1), mb = s2u(mbar);
        if (tid == 0) {
            mbar_init(mb, 1);      mbar_init(mb + 8, 1);
            mbar_expect(mb, 2048); mbar_expect(mb + 8, 2048);
            wait_flag(&g_oflag[0]);
            sh1[0] = g_O[0] * L2E;                    // a0[BOS] = O[0][BOS]
        }
        __syncthreads();
        cl_sync();
        uint32_t rA = 0, rM = 0;
        if (lane < CL) {
            rA = mapa_(b1 + rank * 128u + 8u * (uint32_t)w, (uint32_t)lane);
            rM = mapa_(mb, (uint32_t)lane);
        }
        wait_flag(&g_oflag[1]);
        float2 ov = *(const float2*)&g_O[(size_t)VV + u0];
        float o0 = ov.x * L2E, o1 = ov.y * L2E;

#pragma unroll 1
        for (int si = 0; si < NSEQ - 1; si++) {
            const uint32_t p = (uint32_t)(si & 1);
            if (si) {
                mbar_wait(mb + 8 * p, (uint32_t)(((si - 1) >> 1) & 1));
                if (tid == 0) mbar_expect(mb + 8 * p, 2048);
            }
            const float* cbuf = sh1 + p * 512;
            const float offc = cbuf[0];               // a[BOS] as offset
            sh2[p * 512 + tid] = ex2f_(cbuf[tid] - offc);
            __syncthreads();
            const ulonglong2* ep = (const ulonglong2*)(sh2 + p * 512);
            ulonglong2 A = ep[lane], B = ep[lane + 32], C = ep[lane + 64], D = ep[lane + 96];
            uint64_t p0=0,p1=0,q0=0,q1=0;
            p0=fma2(A.x,e0p[0],p0); p1=fma2(A.y,e0p[1],p1);
            q0=fma2(A.x,e1p[0],q0); q1=fma2(A.y,e1p[1],q1);
            p0=fma2(B.x,e0p[2],p0); p1=fma2(B.y,e0p[3],p1);
            q0=fma2(B.x,e1p[2],q0); q1=fma2(B.y,e1p[3],q1);
            p0=fma2(C.x,e0p[4],p0); p1=fma2(C.y,e0p[5],p1);
            q0=fma2(C.x,e1p[4],q0); q1=fma2(C.y,e1p[5],q1);
            p0=fma2(D.x,e0p[6],p0); p1=fma2(D.y,e0p[7],p1);
            q0=fma2(D.x,e1p[6],q0); q1=fma2(D.y,e1p[7],q1);
            float s0 = wsum(sum2(p0) + sum2(p1));
            float s1 = wsum(sum2(q0) + sum2(q1));
            float al0 = o0 + offc + lg2f_(s0);
            float al1 = o1 + offc + lg2f_(s1);
            if (si == NSEQ - 2) {
                if (rank == 0 && tid == 0) out[0] = al1 * LN2;   // a_{n-1}[EOS], EOS=1
            } else {
                const uint32_t np = (uint32_t)((si + 1) & 1);
                if (lane < CL) st_async64(rA + np * 2048u, pack2(al0, al1), rM + 8u * np);
                int row = si + 2;
                wait_flag(&g_oflag[row]);
                float2 onx = *(const float2*)&g_O[(size_t)row * VV + u0];
                o0 = onx.x * L2E; o1 = onx.y * L2E;
            }
        }
        cl_sync();
    } else {
        // ---------------- role C: O-row builders ----------------
        const int b = bid - 32;       // 0..15
        for (int row = b; row < NSEQ; row += 16) {
            wait_flag(&g_hflag[row]);
            sh1[tid] = g_H2[(size_t)row * DD + tid];
            __syncthreads();
            float acc = bl[tid];
            const float* wc = Wl + tid;
#pragma unroll 16
            for (int k = 0; k < DD; k++) acc = fmaf(sh1[k], wc[(size_t)k * VV], acc);
            g_O[(size_t)row * VV + tid] = acc;
            __syncthreads();
            if (tid == 0) st_rel(&g_oflag[row], 1);
        }
    }
}

extern "C" void kernel_launch(void* const* d_in, const int* in_sizes, int n_in,
                              void* d_out, int out_size)
{
    const void*  nums = d_in[0];
    const float* emb  = (const float*)d_in[1];
    const float* Wxh1 = (const float*)d_in[2];
    const float* Whh1 = (const float*)d_in[3];
    const float* b1   = (const float*)d_in[4];
    const float* Wxh2 = (const float*)d_in[5];
    const float* Whh2 = (const float*)d_in[6];
    const float* b2   = (const float*)d_in[7];
    const float* Wl   = (const float*)d_in[8];
    const float* bl   = (const float*)d_in[9];
    const float* Tm   = (const float*)d_in[10];
    float* out = (float*)d_out;

    float *X, *XW;
    cudaGetSymbolAddress((void**)&X,  g_X);
    cudaGetSymbolAddress((void**)&XW, g_XW);

    cudaFuncSetAttribute((const void*)mega, cudaFuncAttributeNonPortableClusterSizeAllowed, 1);

    detect_kernel<<<1, 256>>>((const int*)nums);
    gather_kernel<<<NSEQ, 128>>>(nums, emb);
    expT_kernel<<<VV * VV / 256, 256>>>(Tm);
    zero_flags_kernel<<<NSEQ / 256, 256>>>();

    dim3 gg(512 / 64, NSEQ / 64);
    gemm_bias<<<gg, 256>>>(X, Wxh1, b1, XW);      // XW1 = X@Wxh1 + b1

    cudaLaunchConfig_t cfg = {};
    cfg.gridDim  = dim3(48, 1, 1);                // 3 clusters of 16
    cfg.blockDim = dim3(512, 1, 1);
    cfg.dynamicSmemBytes = 0;
    cfg.stream = 0;
    cudaLaunchAttribute at[1];
    at[0].id = cudaLaunchAttributeClusterDimension;
    at[0].val.clusterDim.x = CL;
    at[0].val.clusterDim.y = 1;
    at[0].val.clusterDim.z = 1;
    cfg.attrs = at;
    cfg.numAttrs = 1;

    cudaLaunchKernelEx(&cfg, mega, Whh1, (const float*)XW, Whh2, Wxh2, b2, Wl, bl, out);
}